// round 7
// baseline (speedup 1.0000x reference)
#include <cuda_runtime.h>
#include <cuda_bf16.h>
#include <cstdint>

#define BB 4096
#define MAXN 12
#define HID 301
#define NT 10
#define PP 9
#define VSTAT 310
#define KP 320          // padded hidden
#define KS 960          // K concat: act [hi|lo|hi], weights [hi|hi|lo]
#define JT 32           // j-cols per block
#define KC 64           // K per chunk
#define NCH 15          // 960/64
#define SROW 72         // smem row stride in halves (144B; conflict-free)

#define A_H (128 * SROW)            // A stage halves
#define BGRU_H (96 * SROW)
#define BGT_H (64 * SROW)
#define STG_GRU ((A_H + BGRU_H) * 2)   // bytes: 32256
#define STG_GT  ((A_H + BGT_H) * 2)    // bytes: 27648
#define GRU_SMEM (3 * STG_GRU)
#define GT_SMEM  (3 * STG_GT + 128 * MAXN * 4)

// ---------------- scratch (device globals; zero-initialized) ----------------
__device__ __align__(16) float d_g[(size_t)BB * 11 * KP];
__device__ __align__(16) float d_hcur[(size_t)BB * KP];
__device__ __align__(16) float d_hin[(size_t)BB * KP];
__device__ __align__(16) __nv_bfloat16 d_hAS[(size_t)BB * KS];
__device__ __align__(16) __nv_bfloat16 d_iAS[(size_t)BB * KS];
__device__ __align__(16) __nv_bfloat16 d_WhhS[960 * KS];   // rows s*320+j
__device__ __align__(16) __nv_bfloat16 d_WgmS[640 * KS];   // rows m*320+j

__device__ __forceinline__ float sigm(float x) { return 1.f / (1.f + __expf(-x)); }
__device__ __forceinline__ void bsplit(float x, __nv_bfloat16& hi, __nv_bfloat16& lo) {
    hi = __float2bfloat16_rn(x);
    lo = __float2bfloat16_rn(x - __bfloat162float(hi));
}
__device__ __forceinline__ void mma_bf16(float c[4], const uint32_t a[4],
                                         uint32_t b0, uint32_t b1) {
    asm volatile(
        "mma.sync.aligned.m16n8k16.row.col.f32.bf16.bf16.f32 "
        "{%0,%1,%2,%3}, {%4,%5,%6,%7}, {%8,%9}, {%0,%1,%2,%3};"
        : "+f"(c[0]), "+f"(c[1]), "+f"(c[2]), "+f"(c[3])
        : "r"(a[0]), "r"(a[1]), "r"(a[2]), "r"(a[3]), "r"(b0), "r"(b1));
}
__device__ __forceinline__ void cpa16(uint32_t s, const void* g) {
    asm volatile("cp.async.ca.shared.global [%0], [%1], 16;" :: "r"(s), "l"(g));
}
#define CP_COMMIT() asm volatile("cp.async.commit_group;")
template<int N> __device__ __forceinline__ void cp_wait() {
    asm volatile("cp.async.wait_group %0;" :: "n"(N));
}

// ---------------- weight repack + bf16 split (pads stay zero) ---------------
__global__ void k_pad(const float* __restrict__ Whh, const float* __restrict__ Wg,
                      const float* __restrict__ Wm)
{
    int idx = blockIdx.x * blockDim.x + threadIdx.x;
    const int total = HID * HID;
    if (idx < 3 * total) {
        int s = idx / total, r = idx - s * total, j = r / HID, k = r - j * HID;
        __nv_bfloat16 hi, lo;
        bsplit(Whh[(s * HID + j) * HID + k], hi, lo);
        size_t row = (size_t)(s * KP + j) * KS;
        d_WhhS[row + k] = hi; d_WhhS[row + KP + k] = hi; d_WhhS[row + 2 * KP + k] = lo;
    } else if (idx < 5 * total) {
        int m = (idx - 3 * total) / total, r = (idx - 3 * total) % total;
        int j = r / HID, k = r - j * HID;
        const float* W = m ? Wm : Wg;
        __nv_bfloat16 hi, lo;
        bsplit(W[j * VSTAT + k], hi, lo);
        size_t row = (size_t)(m * KP + j) * KS;
        d_WgmS[row + k] = hi; d_WgmS[row + KP + k] = hi; d_WgmS[row + 2 * KP + k] = lo;
    }
}

// ---------------- node 0: h0 = gru(x0, 0) -----------------------------------
__global__ void k_h0(const int* __restrict__ types, const int* __restrict__ paths,
                     const float* __restrict__ W_ih, const float* __restrict__ b_ih,
                     const float* __restrict__ b_hh)
{
    int idx = blockIdx.x * blockDim.x + threadIdx.x;
    if (idx >= BB * HID) return;
    int b = idx / HID, j = idx - b * HID;
    int t = types[b * MAXN], p = paths[b * MAXN];
    float ir  = W_ih[j * 19 + t]            + W_ih[j * 19 + NT + p]            + b_ih[j];
    float iz  = W_ih[(j + HID) * 19 + t]    + W_ih[(j + HID) * 19 + NT + p]    + b_ih[j + HID];
    float inn = W_ih[(j + 2*HID) * 19 + t]  + W_ih[(j + 2*HID) * 19 + NT + p]  + b_ih[j + 2*HID];
    float r = sigm(ir + b_hh[j]);
    float z = sigm(iz + b_hh[j + HID]);
    float n = tanhf(inn + r * b_hh[j + 2*HID]);
    float h = (1.f - z) * n;
    d_hcur[(size_t)b * KP + j] = h;
    __nv_bfloat16 hi, lo; bsplit(h, hi, lo);
    size_t o = (size_t)b * KS + j;
    d_hAS[o] = hi; d_hAS[o + KP] = lo; d_hAS[o + 2 * KP] = hi;
}

// ============================================================================
// Fused GRU GEMM+epilogue. 128 batch x 32 j x 3 gates, K=960 bf16.
// 3-stage cp.async pipeline, K-chunk 64, ONE barrier per chunk.
// ============================================================================
__global__ void __launch_bounds__(256, 2) k_ggru(int v,
    const int* __restrict__ types, const int* __restrict__ paths,
    const float* __restrict__ W_ih,
    const float* __restrict__ b_ih, const float* __restrict__ b_hh)
{
    extern __shared__ __nv_bfloat16 sm[];
    int tid = threadIdx.x, lane = tid & 31, wid = tid >> 5;
    int g = lane >> 2, tig = lane & 3;
    int wm = wid >> 1, wn = wid & 1;
    int b0 = blockIdx.x * 128, j0 = blockIdx.y * JT;

    float c[2][3][2][4];
#pragma unroll
    for (int mf = 0; mf < 2; ++mf)
#pragma unroll
        for (int s = 0; s < 3; ++s)
#pragma unroll
            for (int nf = 0; nf < 2; ++nf)
#pragma unroll
                for (int i = 0; i < 4; ++i) c[mf][s][nf][i] = 0.f;

    uint32_t sbase = (uint32_t)__cvta_generic_to_shared(sm);

    auto loadChunk = [&](int st, int ci) {
        uint32_t sa = sbase + st * STG_GRU;
        uint32_t sbb = sa + A_H * 2;
        int k0 = ci * KC;
        // A: 128 rows x 8 x 16B
#pragma unroll
        for (int q = 0; q < 4; ++q) {
            int idx = tid + 256 * q;
            int r = idx >> 3, sg = idx & 7;
            cpa16(sa + (r * SROW + sg * 8) * 2,
                  d_iAS + (size_t)(b0 + r) * KS + k0 + sg * 8);
        }
        // B: 96 rows x 8 x 16B
#pragma unroll
        for (int q = 0; q < 3; ++q) {
            int idx = tid + 256 * q;
            int r = idx >> 3, sg = idx & 7;
            int s = r >> 5, jt = r & 31;
            cpa16(sbb + (r * SROW + sg * 8) * 2,
                  d_WhhS + (size_t)(s * KP + j0 + jt) * KS + k0 + sg * 8);
        }
    };

    loadChunk(0, 0); CP_COMMIT();
    loadChunk(1, 1); CP_COMMIT();

#pragma unroll 1
    for (int ci = 0; ci < NCH; ++ci) {
        if (ci < NCH - 1) cp_wait<1>(); else cp_wait<0>();
        __syncthreads();
        const __nv_bfloat16* sA = sm + (ci % 3) * (STG_GRU / 2);
        const __nv_bfloat16* sB = sA + A_H;
#pragma unroll
        for (int k16 = 0; k16 < 4; ++k16) {
            int ko = k16 * 16 + 2 * tig;
            uint32_t a[2][4];
#pragma unroll
            for (int mf = 0; mf < 2; ++mf) {
                int mr = wm * 32 + mf * 16 + g;
                a[mf][0] = *(const uint32_t*)&sA[mr * SROW + ko];
                a[mf][1] = *(const uint32_t*)&sA[(mr + 8) * SROW + ko];
                a[mf][2] = *(const uint32_t*)&sA[mr * SROW + ko + 8];
                a[mf][3] = *(const uint32_t*)&sA[(mr + 8) * SROW + ko + 8];
            }
#pragma unroll
            for (int s = 0; s < 3; ++s)
#pragma unroll
                for (int nf = 0; nf < 2; ++nf) {
                    int br = s * 32 + wn * 16 + nf * 8 + g;
                    uint32_t bb0 = *(const uint32_t*)&sB[br * SROW + ko];
                    uint32_t bb1 = *(const uint32_t*)&sB[br * SROW + ko + 8];
#pragma unroll
                    for (int mf = 0; mf < 2; ++mf)
                        mma_bf16(c[mf][s][nf], a[mf], bb0, bb1);
                }
        }
        if (ci + 2 < NCH) { loadChunk((ci + 2) % 3, ci + 2); CP_COMMIT(); }
    }

    // ---- fused GRU epilogue ----
#pragma unroll
    for (int mf = 0; mf < 2; ++mf) {
#pragma unroll
        for (int hf = 0; hf < 2; ++hf) {
            int row = b0 + wm * 32 + mf * 16 + g + hf * 8;
            int t = types[row * MAXN + v], p = paths[row * MAXN + v];
#pragma unroll
            for (int nf = 0; nf < 2; ++nf) {
                int jb = j0 + wn * 16 + nf * 8 + 2 * tig;
                float h2[2];
#pragma unroll
                for (int cl = 0; cl < 2; ++cl) {
                    int j = jb + cl;
                    int ci2 = hf * 2 + cl;
                    float h = 0.f;
                    if (j < HID) {
                        float hin = d_hin[(size_t)row * KP + j];
                        const float* w0 = W_ih + (size_t)j * 19;
                        const float* w1 = W_ih + (size_t)(j + HID) * 19;
                        const float* w2 = W_ih + (size_t)(j + 2 * HID) * 19;
                        float rr = sigm(c[mf][0][nf][ci2] + w0[t] + w0[NT + p] +
                                        b_ih[j] + b_hh[j]);
                        float zz = sigm(c[mf][1][nf][ci2] + w1[t] + w1[NT + p] +
                                        b_ih[j + HID] + b_hh[j + HID]);
                        float nn = tanhf(w2[t] + w2[NT + p] + b_ih[j + 2 * HID] +
                                         rr * (c[mf][2][nf][ci2] + b_hh[j + 2 * HID]));
                        h = (1.f - zz) * nn + zz * hin;
                    }
                    h2[cl] = h;
                }
                *(float2*)&d_hcur[(size_t)row * KP + jb] = make_float2(h2[0], h2[1]);
                __nv_bfloat16 h0h, h0l, h1h, h1l;
                bsplit(h2[0], h0h, h0l); bsplit(h2[1], h1h, h1l);
                size_t o = (size_t)row * KS + jb;
                *(__nv_bfloat162*)(d_hAS + o)          = __nv_bfloat162{h0h, h1h};
                *(__nv_bfloat162*)(d_hAS + o + KP)     = __nv_bfloat162{h0l, h1l};
                *(__nv_bfloat162*)(d_hAS + o + 2 * KP) = __nv_bfloat162{h0h, h1h};
            }
        }
    }
}

// ============================================================================
// Fused gate GEMM+epilogue+hin. 128 batch x 32 j x 2 mats, K=960 bf16.
// Epilogue: g = sigmoid()*(), then hin_{v+1} for this j-slice, iAS splits.
// ============================================================================
__global__ void __launch_bounds__(256, 2) k_ggate(int v,
    const int* __restrict__ paths, const int* __restrict__ adj,
    const float* __restrict__ Wg, const float* __restrict__ bg,
    const float* __restrict__ Wm)
{
    extern __shared__ __nv_bfloat16 sm[];
    float* adjf = (float*)(sm + 3 * (STG_GT / 2));   // [128][12], persists
    int tid = threadIdx.x, lane = tid & 31, wid = tid >> 5;
    int g = lane >> 2, tig = lane & 3;
    int wm = wid >> 1, wn = wid & 1;
    int b0 = blockIdx.x * 128, j0 = blockIdx.y * JT;

    float c[2][2][2][4];
#pragma unroll
    for (int mf = 0; mf < 2; ++mf)
#pragma unroll
        for (int s = 0; s < 2; ++s)
#pragma unroll
            for (int nf = 0; nf < 2; ++nf)
#pragma unroll
                for (int i = 0; i < 4; ++i) c[mf][s][nf][i] = 0.f;

    uint32_t sbase = (uint32_t)__cvta_generic_to_shared(sm);

    auto loadChunk = [&](int st, int ci) {
        uint32_t sa = sbase + st * STG_GT;
        uint32_t sbb = sa + A_H * 2;
        int k0 = ci * KC;
#pragma unroll
        for (int q = 0; q < 4; ++q) {
            int idx = tid + 256 * q;
            int r = idx >> 3, sg = idx & 7;
            cpa16(sa + (r * SROW + sg * 8) * 2,
                  d_hAS + (size_t)(b0 + r) * KS + k0 + sg * 8);
        }
#pragma unroll
        for (int q = 0; q < 2; ++q) {
            int idx = tid + 256 * q;
            int r = idx >> 3, sg = idx & 7;
            int s = r >> 5, jt = r & 31;
            cpa16(sbb + (r * SROW + sg * 8) * 2,
                  d_WgmS + (size_t)(s * KP + j0 + jt) * KS + k0 + sg * 8);
        }
    };

    // stage adjacency row v+1 while pipeline starts
    loadChunk(0, 0); CP_COMMIT();
    loadChunk(1, 1); CP_COMMIT();
    for (int idx = tid; idx < 128 * MAXN; idx += 256) {
        int r = idx / MAXN, u = idx - r * MAXN;
        adjf[idx] = (float)adj[(size_t)(b0 + r) * (MAXN * MAXN) + (v + 1) * MAXN + u];
    }

#pragma unroll 1
    for (int ci = 0; ci < NCH; ++ci) {
        if (ci < NCH - 1) cp_wait<1>(); else cp_wait<0>();
        __syncthreads();
        const __nv_bfloat16* sA = sm + (ci % 3) * (STG_GT / 2);
        const __nv_bfloat16* sB = sA + A_H;
#pragma unroll
        for (int k16 = 0; k16 < 4; ++k16) {
            int ko = k16 * 16 + 2 * tig;
            uint32_t a[2][4];
#pragma unroll
            for (int mf = 0; mf < 2; ++mf) {
                int mr = wm * 32 + mf * 16 + g;
                a[mf][0] = *(const uint32_t*)&sA[mr * SROW + ko];
                a[mf][1] = *(const uint32_t*)&sA[(mr + 8) * SROW + ko];
                a[mf][2] = *(const uint32_t*)&sA[mr * SROW + ko + 8];
                a[mf][3] = *(const uint32_t*)&sA[(mr + 8) * SROW + ko + 8];
            }
#pragma unroll
            for (int s = 0; s < 2; ++s)
#pragma unroll
                for (int nf = 0; nf < 2; ++nf) {
                    int br = s * 32 + wn * 16 + nf * 8 + g;
                    uint32_t bb0 = *(const uint32_t*)&sB[br * SROW + ko];
                    uint32_t bb1 = *(const uint32_t*)&sB[br * SROW + ko + 8];
#pragma unroll
                    for (int mf = 0; mf < 2; ++mf)
                        mma_bf16(c[mf][s][nf], a[mf], bb0, bb1);
                }
        }
        if (ci + 2 < NCH) { loadChunk((ci + 2) % 3, ci + 2); CP_COMMIT(); }
    }

    __syncthreads();                       // stages now dead; reuse for g/hin
    float* g_s   = (float*)sm;             // [128][32]
    float* hin_s = (float*)sm + 128 * JT;  // [128][32]

    // ---- gate epilogue into smem ----
#pragma unroll
    for (int mf = 0; mf < 2; ++mf) {
#pragma unroll
        for (int hf = 0; hf < 2; ++hf) {
            int row = wm * 32 + mf * 16 + g + hf * 8;
            int p = paths[(b0 + row) * MAXN + v];
#pragma unroll
            for (int nf = 0; nf < 2; ++nf) {
                int jl = wn * 16 + nf * 8 + 2 * tig;
#pragma unroll
                for (int cl = 0; cl < 2; ++cl) {
                    int j = j0 + jl + cl;
                    int ci2 = hf * 2 + cl;
                    float val = 0.f;
                    if (j < HID) {
                        float gv = sigm(c[mf][0][nf][ci2] +
                                        Wg[(size_t)j * VSTAT + HID + p] + bg[j]);
                        float mv = c[mf][1][nf][ci2] + Wm[(size_t)j * VSTAT + HID + p];
                        val = gv * mv;
                    }
                    g_s[row * JT + jl + cl] = val;
                }
            }
        }
    }
    __syncthreads();

    // ---- fused hin_{v+1} for this j-slice ----
    for (int idx = tid; idx < 128 * JT; idx += 256) {
        int r = idx / JT, jj = idx - r * JT;
        float acc = 0.f;
        for (int u = 0; u < v; ++u) {
            if (adjf[r * MAXN + u] != 0.f)
                acc += d_g[((size_t)(b0 + r) * 11 + u) * KP + j0 + jj];
        }
        if (adjf[r * MAXN + v] != 0.f) acc += g_s[idx];
        hin_s[idx] = acc;
    }
    __syncthreads();

    // ---- coalesced writes: g, hin, iAS splits ----
    for (int idx = tid; idx < 128 * (JT / 4); idx += 256) {
        int r = idx / (JT / 4), sg = idx - r * (JT / 4);
        float4 g4 = *(float4*)&g_s[r * JT + sg * 4];
        *(float4*)&d_g[((size_t)(b0 + r) * 11 + v) * KP + j0 + sg * 4] = g4;
        float4 h4 = *(float4*)&hin_s[r * JT + sg * 4];
        *(float4*)&d_hin[(size_t)(b0 + r) * KP + j0 + sg * 4] = h4;
        __nv_bfloat16 h0, l0, h1, l1, h2, l2, h3, l3;
        bsplit(h4.x, h0, l0); bsplit(h4.y, h1, l1);
        bsplit(h4.z, h2, l2); bsplit(h4.w, h3, l3);
        size_t o = (size_t)(b0 + r) * KS + j0 + sg * 4;
        __nv_bfloat162* ph_ = (__nv_bfloat162*)(d_iAS + o);
        ph_[0] = __nv_bfloat162{h0, h1}; ph_[1] = __nv_bfloat162{h2, h3};
        __nv_bfloat162* pl_ = (__nv_bfloat162*)(d_iAS + o + KP);
        pl_[0] = __nv_bfloat162{l0, l1}; pl_[1] = __nv_bfloat162{l2, l3};
        __nv_bfloat162* p2_ = (__nv_bfloat162*)(d_iAS + o + 2 * KP);
        p2_[0] = __nv_bfloat162{h0, h1}; p2_[1] = __nv_bfloat162{h2, h3};
    }
}

// ---------------- head ------------------------------------------------------
__global__ void __launch_bounds__(128) k_head(
    const int* __restrict__ paths, const float* __restrict__ feats,
    const float* __restrict__ W_df1, const float* __restrict__ b_df1,
    const float* __restrict__ W_df2, const float* __restrict__ b_df2,
    const float* __restrict__ W_fc1, const float* __restrict__ b_fc1,
    const float* __restrict__ W_fc2, const float* __restrict__ b_fc2,
    float* __restrict__ out)
{
    int b = blockIdx.x;
    int t = threadIdx.x;
    __shared__ float hg[HID + 8];
    __shared__ float df[3 * PP];
    __shared__ float hid16[16];

    for (int j = t; j < HID; j += 128) hg[j] = d_hcur[(size_t)b * KP + j];
    if (t < 3 * PP) df[t] = 0.f;
    __syncthreads();
    if (t == 0) {
        for (int v = 0; v < MAXN; ++v) {
            int base = paths[b * MAXN + v] * 3;
            df[base]     = feats[(b * MAXN + v) * 3 + 0];
            df[base + 1] = feats[(b * MAXN + v) * 3 + 1];
            df[base + 2] = feats[(b * MAXN + v) * 3 + 2];
        }
    }
    __syncthreads();
    if (t < 16) {
        float a = b_df1[t];
        for (int k = 0; k < 3 * PP; ++k) a = fmaf(df[k], W_df1[t * (3 * PP) + k], a);
        hid16[t] = fmaxf(a, 0.f);
    }
    __syncthreads();
    if (t < 8) {
        float a = b_df2[t];
        for (int k = 0; k < 16; ++k) a = fmaf(hid16[k], W_df2[t * 16 + k], a);
        hg[HID + t] = a;
    }
    __syncthreads();
    if (t < 112) {
        const float* W;
        float a;
        int i;
        if (t < 56) { i = t;      W = W_fc1; a = b_fc1[i]; }
        else        { i = t - 56; W = W_fc2; a = b_fc2[i]; }
        const float* wrow = W + i * (HID + 8);
        for (int k = 0; k < HID + 8; ++k) a = fmaf(hg[k], wrow[k], a);
        out[b * 112 + t] = a;
    }
}

// ---------------- launcher --------------------------------------------------
extern "C" void kernel_launch(void* const* d_in, const int* in_sizes, int n_in,
                              void* d_out, int out_size)
{
    const int*   types = (const int*)d_in[0];
    const int*   paths = (const int*)d_in[1];
    const int*   adj   = (const int*)d_in[2];
    const float* feats = (const float*)d_in[3];
    const float* W_ih  = (const float*)d_in[4];
    const float* W_hh  = (const float*)d_in[5];
    const float* b_ih  = (const float*)d_in[6];
    const float* b_hh  = (const float*)d_in[7];
    const float* Wg    = (const float*)d_in[8];
    const float* bg    = (const float*)d_in[9];
    const float* Wm    = (const float*)d_in[10];
    const float* W_df1 = (const float*)d_in[11];
    const float* b_df1 = (const float*)d_in[12];
    const float* W_df2 = (const float*)d_in[13];
    const float* b_df2 = (const float*)d_in[14];
    const float* W_fc1 = (const float*)d_in[15];
    const float* b_fc1 = (const float*)d_in[16];
    const float* W_fc2 = (const float*)d_in[17];
    const float* b_fc2 = (const float*)d_in[18];
    float* out = (float*)d_out;

    cudaFuncSetAttribute(k_ggru,  cudaFuncAttributeMaxDynamicSharedMemorySize, GRU_SMEM);
    cudaFuncSetAttribute(k_ggate, cudaFuncAttributeMaxDynamicSharedMemorySize, GT_SMEM);

    dim3 grid(BB / 128, KP / JT);   // 32 x 10 = 320 blocks

    k_pad<<<(5 * HID * HID + 255) / 256, 256>>>(W_hh, Wg, Wm);
    k_h0<<<(BB * HID + 255) / 256, 256>>>(types, paths, W_ih, b_ih, b_hh);

    k_ggate<<<grid, 256, GT_SMEM>>>(0, paths, adj, Wg, bg, Wm);
    for (int v = 1; v < MAXN; ++v) {
        k_ggru<<<grid, 256, GRU_SMEM>>>(v, types, paths, W_ih, b_ih, b_hh);
        if (v < MAXN - 1)
            k_ggate<<<grid, 256, GT_SMEM>>>(v, paths, adj, Wg, bg, Wm);
    }
    k_head<<<BB, 128>>>(paths, feats, W_df1, b_df1, W_df2, b_df2,
                        W_fc1, b_fc1, W_fc2, b_fc2, out);
}

// round 8
// speedup vs baseline: 1.0099x; 1.0099x over previous
#include <cuda_runtime.h>
#include <cuda_bf16.h>
#include <cstdint>

#define BB 4096
#define MAXN 12
#define HID 301
#define NT 10
#define PP 9
#define VSTAT 310
#define KP 320          // padded hidden
#define KS 960          // K concat: act [hi|lo|hi], weights [hi|hi|lo]
#define JT 32           // j-cols per block
#define KC 64           // K per chunk
#define NCH 15          // 960/64
#define SROW 72         // smem row stride in halves (144B; conflict-free)

#define A_H (128 * SROW)            // A stage halves
#define BGRU_H (96 * SROW)
#define BGT_H (64 * SROW)
#define STG_GRU ((A_H + BGRU_H) * 2)   // bytes
#define STG_GT  ((A_H + BGT_H) * 2)    // bytes
#define GRU_SMEM (3 * STG_GRU)
#define GT_SMEM  (3 * STG_GT + 128 * MAXN * 4)

// ---------------- scratch (device globals; zero-initialized) ----------------
__device__ __align__(16) float d_g[(size_t)BB * 11 * KP];
__device__ __align__(16) float d_hcur[(size_t)BB * KP];
__device__ __align__(16) float d_hin[(size_t)BB * KP];
__device__ __align__(16) __nv_bfloat16 d_hAS[(size_t)BB * KS];
__device__ __align__(16) __nv_bfloat16 d_iAS[(size_t)BB * KS];
__device__ __align__(16) __nv_bfloat16 d_WhhS[960 * KS];   // rows s*320+j
__device__ __align__(16) __nv_bfloat16 d_WgmS[640 * KS];   // rows m*320+j

__device__ __forceinline__ float sigm(float x) { return 1.f / (1.f + __expf(-x)); }
__device__ __forceinline__ void bsplit(float x, __nv_bfloat16& hi, __nv_bfloat16& lo) {
    hi = __float2bfloat16_rn(x);
    lo = __float2bfloat16_rn(x - __bfloat162float(hi));
}
__device__ __forceinline__ void mma_bf16(float c[4], const uint32_t a[4],
                                         uint32_t b0, uint32_t b1) {
    asm volatile(
        "mma.sync.aligned.m16n8k16.row.col.f32.bf16.bf16.f32 "
        "{%0,%1,%2,%3}, {%4,%5,%6,%7}, {%8,%9}, {%0,%1,%2,%3};"
        : "+f"(c[0]), "+f"(c[1]), "+f"(c[2]), "+f"(c[3])
        : "r"(a[0]), "r"(a[1]), "r"(a[2]), "r"(a[3]), "r"(b0), "r"(b1));
}
__device__ __forceinline__ void ldsm4(uint32_t* r, uint32_t addr) {
    asm volatile("ldmatrix.sync.aligned.m8n8.x4.shared.b16 {%0,%1,%2,%3}, [%4];"
                 : "=r"(r[0]), "=r"(r[1]), "=r"(r[2]), "=r"(r[3]) : "r"(addr));
}
__device__ __forceinline__ void cpa16(uint32_t s, const void* g) {
    asm volatile("cp.async.ca.shared.global [%0], [%1], 16;" :: "r"(s), "l"(g));
}
#define CP_COMMIT() asm volatile("cp.async.commit_group;")
template<int N> __device__ __forceinline__ void cp_wait() {
    asm volatile("cp.async.wait_group %0;" :: "n"(N));
}

// ---------------- weight repack + bf16 split (pads stay zero) ---------------
__global__ void k_pad(const float* __restrict__ Whh, const float* __restrict__ Wg,
                      const float* __restrict__ Wm)
{
    int idx = blockIdx.x * blockDim.x + threadIdx.x;
    const int total = HID * HID;
    if (idx < 3 * total) {
        int s = idx / total, r = idx - s * total, j = r / HID, k = r - j * HID;
        __nv_bfloat16 hi, lo;
        bsplit(Whh[(s * HID + j) * HID + k], hi, lo);
        size_t row = (size_t)(s * KP + j) * KS;
        d_WhhS[row + k] = hi; d_WhhS[row + KP + k] = hi; d_WhhS[row + 2 * KP + k] = lo;
    } else if (idx < 5 * total) {
        int m = (idx - 3 * total) / total, r = (idx - 3 * total) % total;
        int j = r / HID, k = r - j * HID;
        const float* W = m ? Wm : Wg;
        __nv_bfloat16 hi, lo;
        bsplit(W[j * VSTAT + k], hi, lo);
        size_t row = (size_t)(m * KP + j) * KS;
        d_WgmS[row + k] = hi; d_WgmS[row + KP + k] = hi; d_WgmS[row + 2 * KP + k] = lo;
    }
}

// ---------------- node 0: h0 = gru(x0, 0) -----------------------------------
__global__ void k_h0(const int* __restrict__ types, const int* __restrict__ paths,
                     const float* __restrict__ W_ih, const float* __restrict__ b_ih,
                     const float* __restrict__ b_hh)
{
    int idx = blockIdx.x * blockDim.x + threadIdx.x;
    if (idx >= BB * HID) return;
    int b = idx / HID, j = idx - b * HID;
    int t = types[b * MAXN], p = paths[b * MAXN];
    float ir  = W_ih[j * 19 + t]            + W_ih[j * 19 + NT + p]            + b_ih[j];
    float iz  = W_ih[(j + HID) * 19 + t]    + W_ih[(j + HID) * 19 + NT + p]    + b_ih[j + HID];
    float inn = W_ih[(j + 2*HID) * 19 + t]  + W_ih[(j + 2*HID) * 19 + NT + p]  + b_ih[j + 2*HID];
    float r = sigm(ir + b_hh[j]);
    float z = sigm(iz + b_hh[j + HID]);
    float n = tanhf(inn + r * b_hh[j + 2*HID]);
    float h = (1.f - z) * n;
    d_hcur[(size_t)b * KP + j] = h;
    __nv_bfloat16 hi, lo; bsplit(h, hi, lo);
    size_t o = (size_t)b * KS + j;
    d_hAS[o] = hi; d_hAS[o + KP] = lo; d_hAS[o + 2 * KP] = hi;
}

// ============================================================================
// Fused GRU GEMM+epilogue. 128 batch x 32 j x 3 gates, K=960 bf16.
// 3-stage cp.async pipeline, ldmatrix fragment loads, early prefetch issue.
// ============================================================================
__global__ void __launch_bounds__(256, 2) k_ggru(int v,
    const int* __restrict__ types, const int* __restrict__ paths,
    const float* __restrict__ W_ih,
    const float* __restrict__ b_ih, const float* __restrict__ b_hh)
{
    extern __shared__ __nv_bfloat16 sm[];
    int tid = threadIdx.x, lane = tid & 31, wid = tid >> 5;
    int g = lane >> 2, tig = lane & 3;
    int li = lane >> 3, lt = lane & 7;          // ldmatrix row decomposition
    int wm = wid >> 1, wn = wid & 1;
    int b0 = blockIdx.x * 128, j0 = blockIdx.y * JT;

    float c[2][3][2][4];
#pragma unroll
    for (int mf = 0; mf < 2; ++mf)
#pragma unroll
        for (int s = 0; s < 3; ++s)
#pragma unroll
            for (int nf = 0; nf < 2; ++nf)
#pragma unroll
                for (int i = 0; i < 4; ++i) c[mf][s][nf][i] = 0.f;

    uint32_t sbase = (uint32_t)__cvta_generic_to_shared(sm);

    // ldmatrix per-lane byte offsets (within a stage)
    uint32_t aoff[2], boff[3];
#pragma unroll
    for (int mf = 0; mf < 2; ++mf) {
        int mrow = wm * 32 + mf * 16 + (li & 1) * 8 + lt;
        aoff[mf] = (uint32_t)(mrow * SROW + (li >> 1) * 8) * 2;
    }
#pragma unroll
    for (int q = 0; q < 3; ++q) {
        int cmb = 2 * q + (li >> 1);            // combo = s*2+nf
        int s = cmb >> 1, nf = cmb & 1;
        int nrow = s * 32 + wn * 16 + nf * 8 + lt;
        boff[q] = (uint32_t)(A_H + nrow * SROW + (li & 1) * 8) * 2;
    }

    auto loadChunk = [&](int st, int ci) {
        uint32_t sa = sbase + st * STG_GRU;
        uint32_t sbb = sa + A_H * 2;
        int k0 = ci * KC;
#pragma unroll
        for (int q = 0; q < 4; ++q) {
            int idx = tid + 256 * q;
            int r = idx >> 3, sg = idx & 7;
            cpa16(sa + (r * SROW + sg * 8) * 2,
                  d_iAS + (size_t)(b0 + r) * KS + k0 + sg * 8);
        }
#pragma unroll
        for (int q = 0; q < 3; ++q) {
            int idx = tid + 256 * q;
            int r = idx >> 3, sg = idx & 7;
            int s = r >> 5, jt = r & 31;
            cpa16(sbb + (r * SROW + sg * 8) * 2,
                  d_WhhS + (size_t)(s * KP + j0 + jt) * KS + k0 + sg * 8);
        }
    };

    loadChunk(0, 0); CP_COMMIT();
    loadChunk(1, 1); CP_COMMIT();

#pragma unroll 1
    for (int ci = 0; ci < NCH; ++ci) {
        if (ci < NCH - 1) cp_wait<1>(); else cp_wait<0>();
        __syncthreads();
        if (ci + 2 < NCH) { loadChunk((ci + 2) % 3, ci + 2); CP_COMMIT(); }
        uint32_t stg = sbase + (ci % 3) * STG_GRU;
#pragma unroll
        for (int k16 = 0; k16 < 4; ++k16) {
            uint32_t ko2 = (uint32_t)(k16 * 16) * 2;
            uint32_t a0[4], a1[4];
            ldsm4(a0, stg + aoff[0] + ko2);
            ldsm4(a1, stg + aoff[1] + ko2);
#pragma unroll
            for (int q = 0; q < 3; ++q) {
                uint32_t bb[4];
                ldsm4(bb, stg + boff[q] + ko2);
#pragma unroll
                for (int hf = 0; hf < 2; ++hf) {
                    int cmb = 2 * q + hf;
                    int s = cmb >> 1, nf = cmb & 1;
                    mma_bf16(c[0][s][nf], a0, bb[2 * hf], bb[2 * hf + 1]);
                    mma_bf16(c[1][s][nf], a1, bb[2 * hf], bb[2 * hf + 1]);
                }
            }
        }
    }

    // ---- fused GRU epilogue ----
#pragma unroll
    for (int mf = 0; mf < 2; ++mf) {
#pragma unroll
        for (int hf = 0; hf < 2; ++hf) {
            int row = b0 + wm * 32 + mf * 16 + g + hf * 8;
            int t = types[row * MAXN + v], p = paths[row * MAXN + v];
#pragma unroll
            for (int nf = 0; nf < 2; ++nf) {
                int jb = j0 + wn * 16 + nf * 8 + 2 * tig;
                float h2[2];
#pragma unroll
                for (int cl = 0; cl < 2; ++cl) {
                    int j = jb + cl;
                    int ci2 = hf * 2 + cl;
                    float h = 0.f;
                    if (j < HID) {
                        float hin = d_hin[(size_t)row * KP + j];
                        const float* w0 = W_ih + (size_t)j * 19;
                        const float* w1 = W_ih + (size_t)(j + HID) * 19;
                        const float* w2 = W_ih + (size_t)(j + 2 * HID) * 19;
                        float rr = sigm(c[mf][0][nf][ci2] + w0[t] + w0[NT + p] +
                                        b_ih[j] + b_hh[j]);
                        float zz = sigm(c[mf][1][nf][ci2] + w1[t] + w1[NT + p] +
                                        b_ih[j + HID] + b_hh[j + HID]);
                        float nn = tanhf(w2[t] + w2[NT + p] + b_ih[j + 2 * HID] +
                                         rr * (c[mf][2][nf][ci2] + b_hh[j + 2 * HID]));
                        h = (1.f - zz) * nn + zz * hin;
                    }
                    h2[cl] = h;
                }
                *(float2*)&d_hcur[(size_t)row * KP + jb] = make_float2(h2[0], h2[1]);
                __nv_bfloat16 h0h, h0l, h1h, h1l;
                bsplit(h2[0], h0h, h0l); bsplit(h2[1], h1h, h1l);
                size_t o = (size_t)row * KS + jb;
                *(__nv_bfloat162*)(d_hAS + o)          = __nv_bfloat162{h0h, h1h};
                *(__nv_bfloat162*)(d_hAS + o + KP)     = __nv_bfloat162{h0l, h1l};
                *(__nv_bfloat162*)(d_hAS + o + 2 * KP) = __nv_bfloat162{h0h, h1h};
            }
        }
    }
}

// ============================================================================
// Fused gate GEMM+epilogue+hin. 128 batch x 32 j x 2 mats, K=960 bf16.
// ============================================================================
__global__ void __launch_bounds__(256, 2) k_ggate(int v,
    const int* __restrict__ paths, const int* __restrict__ adj,
    const float* __restrict__ Wg, const float* __restrict__ bg,
    const float* __restrict__ Wm)
{
    extern __shared__ __nv_bfloat16 sm[];
    float* adjf = (float*)(sm + 3 * (STG_GT / 2));   // [128][12], persists
    int tid = threadIdx.x, lane = tid & 31, wid = tid >> 5;
    int g = lane >> 2, tig = lane & 3;
    int li = lane >> 3, lt = lane & 7;
    int wm = wid >> 1, wn = wid & 1;
    int b0 = blockIdx.x * 128, j0 = blockIdx.y * JT;

    float c[2][2][2][4];
#pragma unroll
    for (int mf = 0; mf < 2; ++mf)
#pragma unroll
        for (int s = 0; s < 2; ++s)
#pragma unroll
            for (int nf = 0; nf < 2; ++nf)
#pragma unroll
                for (int i = 0; i < 4; ++i) c[mf][s][nf][i] = 0.f;

    uint32_t sbase = (uint32_t)__cvta_generic_to_shared(sm);

    uint32_t aoff[2], boff[2];
#pragma unroll
    for (int mf = 0; mf < 2; ++mf) {
        int mrow = wm * 32 + mf * 16 + (li & 1) * 8 + lt;
        aoff[mf] = (uint32_t)(mrow * SROW + (li >> 1) * 8) * 2;
    }
#pragma unroll
    for (int q = 0; q < 2; ++q) {
        int cmb = 2 * q + (li >> 1);
        int s = cmb >> 1, nf = cmb & 1;
        int nrow = s * 32 + wn * 16 + nf * 8 + lt;
        boff[q] = (uint32_t)(A_H + nrow * SROW + (li & 1) * 8) * 2;
    }

    auto loadChunk = [&](int st, int ci) {
        uint32_t sa = sbase + st * STG_GT;
        uint32_t sbb = sa + A_H * 2;
        int k0 = ci * KC;
#pragma unroll
        for (int q = 0; q < 4; ++q) {
            int idx = tid + 256 * q;
            int r = idx >> 3, sg = idx & 7;
            cpa16(sa + (r * SROW + sg * 8) * 2,
                  d_hAS + (size_t)(b0 + r) * KS + k0 + sg * 8);
        }
#pragma unroll
        for (int q = 0; q < 2; ++q) {
            int idx = tid + 256 * q;
            int r = idx >> 3, sg = idx & 7;
            int s = r >> 5, jt = r & 31;
            cpa16(sbb + (r * SROW + sg * 8) * 2,
                  d_WgmS + (size_t)(s * KP + j0 + jt) * KS + k0 + sg * 8);
        }
    };

    loadChunk(0, 0); CP_COMMIT();
    loadChunk(1, 1); CP_COMMIT();
    for (int idx = tid; idx < 128 * MAXN; idx += 256) {
        int r = idx / MAXN, u = idx - r * MAXN;
        adjf[idx] = (float)adj[(size_t)(b0 + r) * (MAXN * MAXN) + (v + 1) * MAXN + u];
    }

#pragma unroll 1
    for (int ci = 0; ci < NCH; ++ci) {
        if (ci < NCH - 1) cp_wait<1>(); else cp_wait<0>();
        __syncthreads();
        if (ci + 2 < NCH) { loadChunk((ci + 2) % 3, ci + 2); CP_COMMIT(); }
        uint32_t stg = sbase + (ci % 3) * STG_GT;
#pragma unroll
        for (int k16 = 0; k16 < 4; ++k16) {
            uint32_t ko2 = (uint32_t)(k16 * 16) * 2;
            uint32_t a0[4], a1[4];
            ldsm4(a0, stg + aoff[0] + ko2);
            ldsm4(a1, stg + aoff[1] + ko2);
#pragma unroll
            for (int q = 0; q < 2; ++q) {
                uint32_t bb[4];
                ldsm4(bb, stg + boff[q] + ko2);
#pragma unroll
                for (int hf = 0; hf < 2; ++hf) {
                    int cmb = 2 * q + hf;
                    int s = cmb >> 1, nf = cmb & 1;
                    mma_bf16(c[0][s][nf], a0, bb[2 * hf], bb[2 * hf + 1]);
                    mma_bf16(c[1][s][nf], a1, bb[2 * hf], bb[2 * hf + 1]);
                }
            }
        }
    }

    __syncthreads();                       // stages now dead; reuse for g/hin
    float* g_s   = (float*)sm;             // [128][32]
    float* hin_s = (float*)sm + 128 * JT;  // [128][32]

    // ---- gate epilogue into smem ----
#pragma unroll
    for (int mf = 0; mf < 2; ++mf) {
#pragma unroll
        for (int hf = 0; hf < 2; ++hf) {
            int row = wm * 32 + mf * 16 + g + hf * 8;
            int p = paths[(b0 + row) * MAXN + v];
#pragma unroll
            for (int nf = 0; nf < 2; ++nf) {
                int jl = wn * 16 + nf * 8 + 2 * tig;
#pragma unroll
                for (int cl = 0; cl < 2; ++cl) {
                    int j = j0 + jl + cl;
                    int ci2 = hf * 2 + cl;
                    float val = 0.f;
                    if (j < HID) {
                        float gv = sigm(c[mf][0][nf][ci2] +
                                        Wg[(size_t)j * VSTAT + HID + p] + bg[j]);
                        float mv = c[mf][1][nf][ci2] + Wm[(size_t)j * VSTAT + HID + p];
                        val = gv * mv;
                    }
                    g_s[row * JT + jl + cl] = val;
                }
            }
        }
    }
    __syncthreads();

    // ---- fused hin_{v+1} for this j-slice ----
    for (int idx = tid; idx < 128 * JT; idx += 256) {
        int r = idx / JT, jj = idx - r * JT;
        float acc = 0.f;
        for (int u = 0; u < v; ++u) {
            if (adjf[r * MAXN + u] != 0.f)
                acc += d_g[((size_t)(b0 + r) * 11 + u) * KP + j0 + jj];
        }
        if (adjf[r * MAXN + v] != 0.f) acc += g_s[idx];
        hin_s[idx] = acc;
    }
    __syncthreads();

    // ---- coalesced writes: g, hin, iAS splits ----
    for (int idx = tid; idx < 128 * (JT / 4); idx += 256) {
        int r = idx / (JT / 4), sg = idx - r * (JT / 4);
        float4 g4 = *(float4*)&g_s[r * JT + sg * 4];
        *(float4*)&d_g[((size_t)(b0 + r) * 11 + v) * KP + j0 + sg * 4] = g4;
        float4 h4 = *(float4*)&hin_s[r * JT + sg * 4];
        *(float4*)&d_hin[(size_t)(b0 + r) * KP + j0 + sg * 4] = h4;
        __nv_bfloat16 h0, l0, h1, l1, h2, l2, h3, l3;
        bsplit(h4.x, h0, l0); bsplit(h4.y, h1, l1);
        bsplit(h4.z, h2, l2); bsplit(h4.w, h3, l3);
        size_t o = (size_t)(b0 + r) * KS + j0 + sg * 4;
        __nv_bfloat162* ph_ = (__nv_bfloat162*)(d_iAS + o);
        ph_[0] = __nv_bfloat162{h0, h1}; ph_[1] = __nv_bfloat162{h2, h3};
        __nv_bfloat162* pl_ = (__nv_bfloat162*)(d_iAS + o + KP);
        pl_[0] = __nv_bfloat162{l0, l1}; pl_[1] = __nv_bfloat162{l2, l3};
        __nv_bfloat162* p2_ = (__nv_bfloat162*)(d_iAS + o + 2 * KP);
        p2_[0] = __nv_bfloat162{h0, h1}; p2_[1] = __nv_bfloat162{h2, h3};
    }
}

// ---------------- head ------------------------------------------------------
__global__ void __launch_bounds__(128) k_head(
    const int* __restrict__ paths, const float* __restrict__ feats,
    const float* __restrict__ W_df1, const float* __restrict__ b_df1,
    const float* __restrict__ W_df2, const float* __restrict__ b_df2,
    const float* __restrict__ W_fc1, const float* __restrict__ b_fc1,
    const float* __restrict__ W_fc2, const float* __restrict__ b_fc2,
    float* __restrict__ out)
{
    int b = blockIdx.x;
    int t = threadIdx.x;
    __shared__ float hg[HID + 8];
    __shared__ float df[3 * PP];
    __shared__ float hid16[16];

    for (int j = t; j < HID; j += 128) hg[j] = d_hcur[(size_t)b * KP + j];
    if (t < 3 * PP) df[t] = 0.f;
    __syncthreads();
    if (t == 0) {
        for (int v = 0; v < MAXN; ++v) {
            int base = paths[b * MAXN + v] * 3;
            df[base]     = feats[(b * MAXN + v) * 3 + 0];
            df[base + 1] = feats[(b * MAXN + v) * 3 + 1];
            df[base + 2] = feats[(b * MAXN + v) * 3 + 2];
        }
    }
    __syncthreads();
    if (t < 16) {
        float a = b_df1[t];
        for (int k = 0; k < 3 * PP; ++k) a = fmaf(df[k], W_df1[t * (3 * PP) + k], a);
        hid16[t] = fmaxf(a, 0.f);
    }
    __syncthreads();
    if (t < 8) {
        float a = b_df2[t];
        for (int k = 0; k < 16; ++k) a = fmaf(hid16[k], W_df2[t * 16 + k], a);
        hg[HID + t] = a;
    }
    __syncthreads();
    if (t < 112) {
        const float* W;
        float a;
        int i;
        if (t < 56) { i = t;      W = W_fc1; a = b_fc1[i]; }
        else        { i = t - 56; W = W_fc2; a = b_fc2[i]; }
        const float* wrow = W + i * (HID + 8);
        for (int k = 0; k < HID + 8; ++k) a = fmaf(hg[k], wrow[k], a);
        out[b * 112 + t] = a;
    }
}

// ---------------- launcher --------------------------------------------------
extern "C" void kernel_launch(void* const* d_in, const int* in_sizes, int n_in,
                              void* d_out, int out_size)
{
    const int*   types = (const int*)d_in[0];
    const int*   paths = (const int*)d_in[1];
    const int*   adj   = (const int*)d_in[2];
    const float* feats = (const float*)d_in[3];
    const float* W_ih  = (const float*)d_in[4];
    const float* W_hh  = (const float*)d_in[5];
    const float* b_ih  = (const float*)d_in[6];
    const float* b_hh  = (const float*)d_in[7];
    const float* Wg    = (const float*)d_in[8];
    const float* bg    = (const float*)d_in[9];
    const float* Wm    = (const float*)d_in[10];
    const float* W_df1 = (const float*)d_in[11];
    const float* b_df1 = (const float*)d_in[12];
    const float* W_df2 = (const float*)d_in[13];
    const float* b_df2 = (const float*)d_in[14];
    const float* W_fc1 = (const float*)d_in[15];
    const float* b_fc1 = (const float*)d_in[16];
    const float* W_fc2 = (const float*)d_in[17];
    const float* b_fc2 = (const float*)d_in[18];
    float* out = (float*)d_out;

    cudaFuncSetAttribute(k_ggru,  cudaFuncAttributeMaxDynamicSharedMemorySize, GRU_SMEM);
    cudaFuncSetAttribute(k_ggate, cudaFuncAttributeMaxDynamicSharedMemorySize, GT_SMEM);

    dim3 grid(BB / 128, KP / JT);   // 32 x 10 = 320 blocks

    k_pad<<<(5 * HID * HID + 255) / 256, 256>>>(W_hh, Wg, Wm);
    k_h0<<<(BB * HID + 255) / 256, 256>>>(types, paths, W_ih, b_ih, b_hh);

    k_ggate<<<grid, 256, GT_SMEM>>>(0, paths, adj, Wg, bg, Wm);
    for (int v = 1; v < MAXN; ++v) {
        k_ggru<<<grid, 256, GRU_SMEM>>>(v, types, paths, W_ih, b_ih, b_hh);
        if (v < MAXN - 1)
            k_ggate<<<grid, 256, GT_SMEM>>>(v, paths, adj, Wg, bg, Wm);
    }
    k_head<<<BB, 128>>>(paths, feats, W_df1, b_df1, W_df2, b_df2,
                        W_fc1, b_fc1, W_fc2, b_fc2, out);
}